// round 1
// baseline (speedup 1.0000x reference)
#include <cuda_runtime.h>
#include <math.h>

#define D       256
#define BATCH   128
#define SEQ     1024
#define ROWS    (BATCH*SEQ)          // 131072
#define NCHUNK  8                    // S split for pass-A partials
#define GBLOCKS 1024                 // blocks for pass B / C (8 warps each -> 8192 warps, 16 rows/warp)
#define NWARPS  8
#define THREADS 256

// ---------------- scratch (device globals; no allocation) ----------------
__device__ __align__(16) float g_part1[BATCH*NCHUNK*D]; // pass-A partial sums [b*8+c][d]
__device__ __align__(16) float g_c1[BATCH*D];           // per-batch centroid
__device__ __align__(16) float g_mean[D];               // global Frechet-ish mean
__device__ __align__(16) float g_psum[GBLOCKS*D];       // per-block sum(x_t)
__device__ __align__(16) float g_psq[GBLOCKS*D];        // per-block sum(x_t^2)
__device__ __align__(16) float g_scale[D];              // gamma / sqrt(var+eps)

// ---------------- helpers ----------------
__device__ __forceinline__ float wsum(float v) {
    #pragma unroll
    for (int o = 16; o > 0; o >>= 1) v += __shfl_xor_sync(0xffffffffu, v, o);
    return v;
}

// block-wide sum over 256 threads, broadcast to all
__device__ __forceinline__ float block_sum_bcast(float v, float* sh) {
    v = wsum(v);
    int w = threadIdx.x >> 5;
    if ((threadIdx.x & 31) == 0) sh[w] = v;
    __syncthreads();
    if (threadIdx.x < 8) {
        float t = sh[threadIdx.x];
        #pragma unroll
        for (int o = 4; o > 0; o >>= 1) t += __shfl_xor_sync(0xffu, t, o);
        if (threadIdx.x == 0) sh[0] = t;
    }
    __syncthreads();
    float r = sh[0];
    __syncthreads();
    return r;
}

// ---------------- kernel 1: partial sums over seq chunks ----------------
// grid = BATCH*NCHUNK (1024), block = 256. Rows are contiguous: block blk owns rows [blk*128, blk*128+128)
__global__ void __launch_bounds__(THREADS) k_sum_seq(const float* __restrict__ x) {
    int blk = blockIdx.x;
    int d = threadIdx.x;
    const float* p = x + (size_t)blk * 128 * D + d;
    float a0 = 0.f, a1 = 0.f, a2 = 0.f, a3 = 0.f;
    #pragma unroll 8
    for (int s = 0; s < 128; s += 4) {
        a0 += p[(size_t)(s + 0) * D];
        a1 += p[(size_t)(s + 1) * D];
        a2 += p[(size_t)(s + 2) * D];
        a3 += p[(size_t)(s + 3) * D];
    }
    g_part1[blk * D + d] = (a0 + a1) + (a2 + a3);
}

// ---------------- kernel 2: per-batch centroid ----------------
// grid = BATCH, block = 256
__global__ void __launch_bounds__(THREADS) k_centroid_b() {
    __shared__ float sh[8];
    int b = blockIdx.x, d = threadIdx.x;
    float s = 0.f;
    #pragma unroll
    for (int c = 0; c < NCHUNK; c++) s += g_part1[(b * NCHUNK + c) * D + d];
    float avg = s * (1.0f / SEQ);
    float contrib = (d == 0) ? -avg * avg : avg * avg;     // linner(avg,avg)
    float lin = block_sum_bcast(contrib, sh);
    float denom = sqrtf(fmaxf(fabsf(lin), 1e-8f));
    g_c1[b * D + d] = avg / denom;
}

// ---------------- kernel 3: centroid over batch -> mean ----------------
// grid = 1, block = 256
__global__ void __launch_bounds__(THREADS) k_centroid_mean() {
    __shared__ float sh[8];
    int d = threadIdx.x;
    float s = 0.f;
    #pragma unroll 8
    for (int b = 0; b < BATCH; b++) s += g_c1[b * D + d];
    float avg = s * (1.0f / BATCH);
    float contrib = (d == 0) ? -avg * avg : avg * avg;
    float lin = block_sum_bcast(contrib, sh);
    float denom = sqrtf(fmaxf(fabsf(lin), 1e-8f));
    g_mean[d] = avg / denom;
}

// ---------------- kernel 4: pass B — per-feature sum & sumsq of x_t ----------------
// grid = GBLOCKS, block = 256 (8 warps). Warp per row; lane owns d in {4l..4l+3, 128+4l..131+4l}.
__global__ void __launch_bounds__(THREADS) k_stats(const float* __restrict__ x) {
    __shared__ __align__(16) float sh_s[NWARPS * D]; // 8 KB
    __shared__ __align__(16) float sh_q[NWARPS * D]; // 8 KB
    const int lane = threadIdx.x & 31, warp = threadIdx.x >> 5;
    const int gw = blockIdx.x * NWARPS + warp;
    const float4* X = (const float4*)x;

    float4 m0 = ((const float4*)g_mean)[lane];
    float4 m1 = ((const float4*)g_mean)[32 + lane];
    const float mean0 = __shfl_sync(0xffffffffu, m0.x, 0);
    const float inv1pm0 = 1.0f / (1.0f + mean0);
    float4 ma0 = m0, ma1 = m1;                 // mean + origin
    if (lane == 0) ma0.x += 1.0f;

    float4 s0 = {0,0,0,0}, s1 = {0,0,0,0}, q0 = {0,0,0,0}, q1 = {0,0,0,0};

    for (int row = gw; row < ROWS; row += GBLOCKS * NWARPS) {
        float4 a = X[(size_t)row * 64 + lane];
        float4 b = X[(size_t)row * 64 + 32 + lane];
        // alpha = -linner(mean, x) = mean0*x0 - sum_{d>0} mean_d x_d = 2*mean0*x0 - full_dot
        float dp = a.x*m0.x + a.y*m0.y + a.z*m0.z + a.w*m0.w
                 + b.x*m1.x + b.y*m1.y + b.z*m1.z + b.w*m1.w;
        dp = wsum(dp);
        float x0 = __shfl_sync(0xffffffffu, a.x, 0);
        float alpha = fmaxf(2.0f * mean0 * x0 - dp, 1.0f + 1e-7f);
        float fac = acoshf(alpha) / sqrtf(alpha * alpha - 1.0f);
        float4 t0, t1;
        t0.x = fac * (a.x - alpha * m0.x); t0.y = fac * (a.y - alpha * m0.y);
        t0.z = fac * (a.z - alpha * m0.z); t0.w = fac * (a.w - alpha * m0.w);
        t1.x = fac * (b.x - alpha * m1.x); t1.y = fac * (b.y - alpha * m1.y);
        t1.z = fac * (b.z - alpha * m1.z); t1.w = fac * (b.w - alpha * m1.w);
        float v0 = __shfl_sync(0xffffffffu, t0.x, 0);
        float coef = v0 * inv1pm0;
        t0.x -= coef * ma0.x; t0.y -= coef * ma0.y; t0.z -= coef * ma0.z; t0.w -= coef * ma0.w;
        t1.x -= coef * ma1.x; t1.y -= coef * ma1.y; t1.z -= coef * ma1.z; t1.w -= coef * ma1.w;
        s0.x += t0.x; s0.y += t0.y; s0.z += t0.z; s0.w += t0.w;
        s1.x += t1.x; s1.y += t1.y; s1.z += t1.z; s1.w += t1.w;
        q0.x += t0.x*t0.x; q0.y += t0.y*t0.y; q0.z += t0.z*t0.z; q0.w += t0.w*t0.w;
        q1.x += t1.x*t1.x; q1.y += t1.y*t1.y; q1.z += t1.z*t1.z; q1.w += t1.w*t1.w;
    }

    ((float4*)(sh_s + warp * D))[lane] = s0;
    ((float4*)(sh_s + warp * D))[32 + lane] = s1;
    ((float4*)(sh_q + warp * D))[lane] = q0;
    ((float4*)(sh_q + warp * D))[32 + lane] = q1;
    __syncthreads();
    int d = threadIdx.x;
    float ts = 0.f, tq = 0.f;
    #pragma unroll
    for (int w = 0; w < NWARPS; w++) { ts += sh_s[w * D + d]; tq += sh_q[w * D + d]; }
    g_psum[blockIdx.x * D + d] = ts;
    g_psq[blockIdx.x * D + d] = tq;
}

// ---------------- kernel 5: variance -> scale ----------------
// grid = D (256 blocks, one per feature), block = 256
__global__ void __launch_bounds__(THREADS) k_var(const float* __restrict__ gamma) {
    __shared__ float sh[8];
    const int d = blockIdx.x, t = threadIdx.x;
    float s = 0.f, q = 0.f;
    #pragma unroll
    for (int g = t; g < GBLOCKS; g += THREADS) { s += g_psum[g * D + d]; q += g_psq[g * D + d]; }
    float S_ = block_sum_bcast(s, sh);
    float Q_ = block_sum_bcast(q, sh);
    if (t == 0) {
        const float invN = 1.0f / (float)ROWS;
        float mu = S_ * invN;
        float var = Q_ * invN - mu * mu;
        g_scale[d] = gamma[0] / sqrtf(var + 1e-5f);
    }
}

// ---------------- kernel 6: pass C — final output ----------------
// grid = GBLOCKS, block = 256
__global__ void __launch_bounds__(THREADS) k_final(const float* __restrict__ x,
                                                   const float* __restrict__ beta,
                                                   float* __restrict__ out) {
    const int lane = threadIdx.x & 31, warp = threadIdx.x >> 5;
    const int gw = blockIdx.x * NWARPS + warp;
    const float4* X = (const float4*)x;
    float4* O = (float4*)out;

    float4 m0 = ((const float4*)g_mean)[lane];
    float4 m1 = ((const float4*)g_mean)[32 + lane];
    const float mean0 = __shfl_sync(0xffffffffu, m0.x, 0);
    const float inv1pm0 = 1.0f / (1.0f + mean0);
    float4 ma0 = m0, ma1 = m1;
    if (lane == 0) ma0.x += 1.0f;

    float4 sc0 = ((const float4*)g_scale)[lane];
    float4 sc1 = ((const float4*)g_scale)[32 + lane];

    float4 bt0 = ((const float4*)beta)[lane];
    float4 bt1 = ((const float4*)beta)[32 + lane];
    const float beta0 = __shfl_sync(0xffffffffu, bt0.x, 0);
    const float inv1pb0 = 1.0f / (1.0f + beta0);
    float4 ba0 = bt0, ba1 = bt1;               // beta + origin
    if (lane == 0) ba0.x += 1.0f;

    for (int row = gw; row < ROWS; row += GBLOCKS * NWARPS) {
        float4 a = X[(size_t)row * 64 + lane];
        float4 b = X[(size_t)row * 64 + 32 + lane];
        float dp = a.x*m0.x + a.y*m0.y + a.z*m0.z + a.w*m0.w
                 + b.x*m1.x + b.y*m1.y + b.z*m1.z + b.w*m1.w;
        dp = wsum(dp);
        float x0 = __shfl_sync(0xffffffffu, a.x, 0);
        float alpha = fmaxf(2.0f * mean0 * x0 - dp, 1.0f + 1e-7f);
        float fac = acoshf(alpha) / sqrtf(alpha * alpha - 1.0f);
        float4 t0, t1;
        t0.x = fac * (a.x - alpha * m0.x); t0.y = fac * (a.y - alpha * m0.y);
        t0.z = fac * (a.z - alpha * m0.z); t0.w = fac * (a.w - alpha * m0.w);
        t1.x = fac * (b.x - alpha * m1.x); t1.y = fac * (b.y - alpha * m1.y);
        t1.z = fac * (b.z - alpha * m1.z); t1.w = fac * (b.w - alpha * m1.w);
        float v0 = __shfl_sync(0xffffffffu, t0.x, 0);
        float coef = v0 * inv1pm0;
        t0.x -= coef * ma0.x; t0.y -= coef * ma0.y; t0.z -= coef * ma0.z; t0.w -= coef * ma0.w;
        t1.x -= coef * ma1.x; t1.y -= coef * ma1.y; t1.z -= coef * ma1.z; t1.w -= coef * ma1.w;

        // scale by gamma/std
        t0.x *= sc0.x; t0.y *= sc0.y; t0.z *= sc0.z; t0.w *= sc0.w;
        t1.x *= sc1.x; t1.y *= sc1.y; t1.z *= sc1.z; t1.w *= sc1.w;

        // transp0(beta, v): lb = linner(beta,v) = full_dot - 2*beta0*v0
        float dbv = t0.x*bt0.x + t0.y*bt0.y + t0.z*bt0.z + t0.w*bt0.w
                  + t1.x*bt1.x + t1.y*bt1.y + t1.z*bt1.z + t1.w*bt1.w;
        dbv = wsum(dbv);
        float v0b = __shfl_sync(0xffffffffu, t0.x, 0);
        float lb = dbv - 2.0f * beta0 * v0b;
        float c2 = lb * inv1pb0;
        float4 u0v, u1v;
        u0v.x = t0.x + c2 * ba0.x; u0v.y = t0.y + c2 * ba0.y;
        u0v.z = t0.z + c2 * ba0.z; u0v.w = t0.w + c2 * ba0.w;
        u1v.x = t1.x + c2 * ba1.x; u1v.y = t1.y + c2 * ba1.y;
        u1v.z = t1.z + c2 * ba1.z; u1v.w = t1.w + c2 * ba1.w;

        // expmap(beta, u): nn = linner(u,u) = full - 2*u0^2
        float uu = u0v.x*u0v.x + u0v.y*u0v.y + u0v.z*u0v.z + u0v.w*u0v.w
                 + u1v.x*u1v.x + u1v.y*u1v.y + u1v.z*u1v.z + u1v.w*u1v.w;
        uu = wsum(uu);
        float u0 = __shfl_sync(0xffffffffu, u0v.x, 0);
        float nn = uu - 2.0f * u0 * u0;
        float n = sqrtf(fmaxf(nn, 1e-7f));
        float ch = coshf(n);
        float shn = sinhf(n) / n;

        float4 o0, o1;
        o0.x = ch * bt0.x + shn * u0v.x; o0.y = ch * bt0.y + shn * u0v.y;
        o0.z = ch * bt0.z + shn * u0v.z; o0.w = ch * bt0.w + shn * u0v.w;
        o1.x = ch * bt1.x + shn * u1v.x; o1.y = ch * bt1.y + shn * u1v.y;
        o1.z = ch * bt1.z + shn * u1v.z; o1.w = ch * bt1.w + shn * u1v.w;
        O[(size_t)row * 64 + lane] = o0;
        O[(size_t)row * 64 + 32 + lane] = o1;
    }
}

// ---------------- launch ----------------
extern "C" void kernel_launch(void* const* d_in, const int* in_sizes, int n_in,
                              void* d_out, int out_size) {
    const float* x     = (const float*)d_in[0];
    const float* beta  = (const float*)d_in[1];
    const float* gamma = (const float*)d_in[2];
    float* out = (float*)d_out;
    (void)in_sizes; (void)n_in; (void)out_size;

    k_sum_seq<<<BATCH * NCHUNK, THREADS>>>(x);
    k_centroid_b<<<BATCH, THREADS>>>();
    k_centroid_mean<<<1, THREADS>>>();
    k_stats<<<GBLOCKS, THREADS>>>(x);
    k_var<<<D, THREADS>>>(gamma);
    k_final<<<GBLOCKS, THREADS>>>(x, beta, out);
}

// round 2
// speedup vs baseline: 1.0334x; 1.0334x over previous
#include <cuda_runtime.h>
#include <math.h>

#define D       256
#define BATCH   128
#define SEQ     1024
#define ROWS    (BATCH*SEQ)          // 131072
#define NCHUNK  8
#define GBLOCKS 1024                 // 8 warps each -> 8192 warps
#define NWARPS  8
#define THREADS 256
#define RPW     (ROWS/(GBLOCKS*NWARPS))   // 16 rows per warp

// ---------------- scratch (device globals; no allocation) ----------------
__device__ __align__(16) float g_part1[BATCH*NCHUNK*D];
__device__ __align__(16) float g_c1[BATCH*D];
__device__ __align__(16) float g_mean[D];
__device__ __align__(16) float g_psum[GBLOCKS*D];
__device__ __align__(16) float g_psq[GBLOCKS*D];
__device__ __align__(16) float g_scale[D];
__device__ __align__(16) float4 g_rowsc[ROWS];   // per-row (fac, fac*alpha, coef, 0)  = 2MB

// ---------------- helpers ----------------
__device__ __forceinline__ float wsum(float v) {
    #pragma unroll
    for (int o = 16; o > 0; o >>= 1) v += __shfl_xor_sync(0xffffffffu, v, o);
    return v;
}
// two independent butterfly chains, interleaved to pipeline SHFL latency
__device__ __forceinline__ void wsum2(float& a, float& b) {
    #pragma unroll
    for (int o = 16; o > 0; o >>= 1) {
        a += __shfl_xor_sync(0xffffffffu, a, o);
        b += __shfl_xor_sync(0xffffffffu, b, o);
    }
}
__device__ __forceinline__ void wsum4(float& a, float& b, float& c, float& d) {
    #pragma unroll
    for (int o = 16; o > 0; o >>= 1) {
        a += __shfl_xor_sync(0xffffffffu, a, o);
        b += __shfl_xor_sync(0xffffffffu, b, o);
        c += __shfl_xor_sync(0xffffffffu, c, o);
        d += __shfl_xor_sync(0xffffffffu, d, o);
    }
}
__device__ __forceinline__ float block_sum_bcast(float v, float* sh) {
    v = wsum(v);
    int w = threadIdx.x >> 5;
    if ((threadIdx.x & 31) == 0) sh[w] = v;
    __syncthreads();
    if (threadIdx.x < 8) {
        float t = sh[threadIdx.x];
        #pragma unroll
        for (int o = 4; o > 0; o >>= 1) t += __shfl_xor_sync(0xffu, t, o);
        if (threadIdx.x == 0) sh[0] = t;
    }
    __syncthreads();
    float r = sh[0];
    __syncthreads();
    return r;
}

// ---------------- kernel 1: partial sums over seq chunks ----------------
__global__ void __launch_bounds__(THREADS) k_sum_seq(const float* __restrict__ x) {
    int blk = blockIdx.x;
    int d = threadIdx.x;
    const float* p = x + (size_t)blk * 128 * D + d;
    float a0 = 0.f, a1 = 0.f, a2 = 0.f, a3 = 0.f;
    #pragma unroll 8
    for (int s = 0; s < 128; s += 4) {
        a0 += p[(size_t)(s + 0) * D];
        a1 += p[(size_t)(s + 1) * D];
        a2 += p[(size_t)(s + 2) * D];
        a3 += p[(size_t)(s + 3) * D];
    }
    g_part1[blk * D + d] = (a0 + a1) + (a2 + a3);
}

// ---------------- kernel 2: per-batch centroid ----------------
__global__ void __launch_bounds__(THREADS) k_centroid_b() {
    __shared__ float sh[8];
    int b = blockIdx.x, d = threadIdx.x;
    float s = 0.f;
    #pragma unroll
    for (int c = 0; c < NCHUNK; c++) s += g_part1[(b * NCHUNK + c) * D + d];
    float avg = s * (1.0f / SEQ);
    float contrib = (d == 0) ? -avg * avg : avg * avg;
    float lin = block_sum_bcast(contrib, sh);
    float denom = sqrtf(fmaxf(fabsf(lin), 1e-8f));
    g_c1[b * D + d] = avg / denom;
}

// ---------------- kernel 3: centroid over batch -> mean ----------------
__global__ void __launch_bounds__(THREADS) k_centroid_mean() {
    __shared__ float sh[8];
    int d = threadIdx.x;
    float s = 0.f;
    #pragma unroll 8
    for (int b = 0; b < BATCH; b++) s += g_c1[b * D + d];
    float avg = s * (1.0f / BATCH);
    float contrib = (d == 0) ? -avg * avg : avg * avg;
    float lin = block_sum_bcast(contrib, sh);
    float denom = sqrtf(fmaxf(fabsf(lin), 1e-8f));
    g_mean[d] = avg / denom;
}

// ---------------- kernel 4: pass B — 2-row ILP stats + per-row scalar cache ----------------
__global__ void __launch_bounds__(THREADS) k_stats(const float* __restrict__ x) {
    __shared__ __align__(16) float sh_s[NWARPS * D];
    __shared__ __align__(16) float sh_q[NWARPS * D];
    const int lane = threadIdx.x & 31, warp = threadIdx.x >> 5;
    const int gw = blockIdx.x * NWARPS + warp;
    const int base = gw * RPW;
    const float4* X = (const float4*)x;

    float4 m0 = ((const float4*)g_mean)[lane];
    float4 m1 = ((const float4*)g_mean)[32 + lane];
    const float mean0 = __shfl_sync(0xffffffffu, m0.x, 0);
    const float inv1pm0 = 1.0f / (1.0f + mean0);
    float4 ma0 = m0, ma1 = m1;                 // mean + origin
    if (lane == 0) ma0.x += 1.0f;

    float4 s0 = {0,0,0,0}, s1 = {0,0,0,0}, q0 = {0,0,0,0}, q1 = {0,0,0,0};

    #pragma unroll 2
    for (int i = 0; i < RPW; i += 2) {
        const int rA = base + i, rB = rA + 1;
        float4 aA = X[(size_t)rA * 64 + lane];
        float4 bA = X[(size_t)rA * 64 + 32 + lane];
        float4 aB = X[(size_t)rB * 64 + lane];
        float4 bB = X[(size_t)rB * 64 + 32 + lane];

        float dpA = aA.x*m0.x + aA.y*m0.y + aA.z*m0.z + aA.w*m0.w
                  + bA.x*m1.x + bA.y*m1.y + bA.z*m1.z + bA.w*m1.w;
        float dpB = aB.x*m0.x + aB.y*m0.y + aB.z*m0.z + aB.w*m0.w
                  + bB.x*m1.x + bB.y*m1.y + bB.z*m1.z + bB.w*m1.w;
        wsum2(dpA, dpB);

        float x0A = __shfl_sync(0xffffffffu, aA.x, 0);
        float x0B = __shfl_sync(0xffffffffu, aB.x, 0);
        float alA = fmaxf(2.0f * mean0 * x0A - dpA, 1.0f + 1e-7f);
        float alB = fmaxf(2.0f * mean0 * x0B - dpB, 1.0f + 1e-7f);
        float facA = acoshf(alA) / sqrtf(alA * alA - 1.0f);
        float facB = acoshf(alB) / sqrtf(alB * alB - 1.0f);

        float4 tA0, tA1, tB0, tB1;
        tA0.x = facA * (aA.x - alA * m0.x); tA0.y = facA * (aA.y - alA * m0.y);
        tA0.z = facA * (aA.z - alA * m0.z); tA0.w = facA * (aA.w - alA * m0.w);
        tA1.x = facA * (bA.x - alA * m1.x); tA1.y = facA * (bA.y - alA * m1.y);
        tA1.z = facA * (bA.z - alA * m1.z); tA1.w = facA * (bA.w - alA * m1.w);
        tB0.x = facB * (aB.x - alB * m0.x); tB0.y = facB * (aB.y - alB * m0.y);
        tB0.z = facB * (aB.z - alB * m0.z); tB0.w = facB * (aB.w - alB * m0.w);
        tB1.x = facB * (bB.x - alB * m1.x); tB1.y = facB * (bB.y - alB * m1.y);
        tB1.z = facB * (bB.z - alB * m1.z); tB1.w = facB * (bB.w - alB * m1.w);

        float v0A = __shfl_sync(0xffffffffu, tA0.x, 0);
        float v0B = __shfl_sync(0xffffffffu, tB0.x, 0);
        float coefA = v0A * inv1pm0;
        float coefB = v0B * inv1pm0;
        tA0.x -= coefA*ma0.x; tA0.y -= coefA*ma0.y; tA0.z -= coefA*ma0.z; tA0.w -= coefA*ma0.w;
        tA1.x -= coefA*ma1.x; tA1.y -= coefA*ma1.y; tA1.z -= coefA*ma1.z; tA1.w -= coefA*ma1.w;
        tB0.x -= coefB*ma0.x; tB0.y -= coefB*ma0.y; tB0.z -= coefB*ma0.z; tB0.w -= coefB*ma0.w;
        tB1.x -= coefB*ma1.x; tB1.y -= coefB*ma1.y; tB1.z -= coefB*ma1.z; tB1.w -= coefB*ma1.w;

        if (lane == 0) {
            g_rowsc[rA] = make_float4(facA, facA * alA, coefA, 0.f);
            g_rowsc[rB] = make_float4(facB, facB * alB, coefB, 0.f);
        }

        s0.x += tA0.x + tB0.x; s0.y += tA0.y + tB0.y; s0.z += tA0.z + tB0.z; s0.w += tA0.w + tB0.w;
        s1.x += tA1.x + tB1.x; s1.y += tA1.y + tB1.y; s1.z += tA1.z + tB1.z; s1.w += tA1.w + tB1.w;
        q0.x += tA0.x*tA0.x + tB0.x*tB0.x; q0.y += tA0.y*tA0.y + tB0.y*tB0.y;
        q0.z += tA0.z*tA0.z + tB0.z*tB0.z; q0.w += tA0.w*tA0.w + tB0.w*tB0.w;
        q1.x += tA1.x*tA1.x + tB1.x*tB1.x; q1.y += tA1.y*tA1.y + tB1.y*tB1.y;
        q1.z += tA1.z*tA1.z + tB1.z*tB1.z; q1.w += tA1.w*tA1.w + tB1.w*tB1.w;
    }

    ((float4*)(sh_s + warp * D))[lane] = s0;
    ((float4*)(sh_s + warp * D))[32 + lane] = s1;
    ((float4*)(sh_q + warp * D))[lane] = q0;
    ((float4*)(sh_q + warp * D))[32 + lane] = q1;
    __syncthreads();
    int d = threadIdx.x;
    float ts = 0.f, tq = 0.f;
    #pragma unroll
    for (int w = 0; w < NWARPS; w++) { ts += sh_s[w * D + d]; tq += sh_q[w * D + d]; }
    g_psum[blockIdx.x * D + d] = ts;
    g_psq[blockIdx.x * D + d] = tq;
}

// ---------------- kernel 5: variance -> scale ----------------
__global__ void __launch_bounds__(THREADS) k_var(const float* __restrict__ gamma) {
    __shared__ float sh[8];
    const int d = blockIdx.x, t = threadIdx.x;
    float s = 0.f, q = 0.f;
    #pragma unroll
    for (int g = t; g < GBLOCKS; g += THREADS) { s += g_psum[g * D + d]; q += g_psq[g * D + d]; }
    float S_ = block_sum_bcast(s, sh);
    float Q_ = block_sum_bcast(q, sh);
    if (t == 0) {
        const float invN = 1.0f / (float)ROWS;
        float mu = S_ * invN;
        float var = Q_ * invN - mu * mu;
        g_scale[d] = gamma[0] / sqrtf(var + 1e-5f);
    }
}

// ---------------- kernel 6: pass C — 2-row ILP, single reduction round ----------------
// Uses cached per-row (fac, fac*alpha, coef); uses identity
// linner(u,u) = linner(t',t') - 2*c2*t'_0  (valid since linner(beta,beta) = -1).
__global__ void __launch_bounds__(THREADS) k_final(const float* __restrict__ x,
                                                   const float* __restrict__ beta,
                                                   float* __restrict__ out) {
    const int lane = threadIdx.x & 31, warp = threadIdx.x >> 5;
    const int gw = blockIdx.x * NWARPS + warp;
    const int base = gw * RPW;
    const float4* X = (const float4*)x;
    float4* O = (float4*)out;

    float4 m0 = ((const float4*)g_mean)[lane];
    float4 m1 = ((const float4*)g_mean)[32 + lane];
    float4 ma0 = m0, ma1 = m1;
    if (lane == 0) ma0.x += 1.0f;

    float4 sc0 = ((const float4*)g_scale)[lane];
    float4 sc1 = ((const float4*)g_scale)[32 + lane];

    float4 bt0 = ((const float4*)beta)[lane];
    float4 bt1 = ((const float4*)beta)[32 + lane];
    const float beta0 = __shfl_sync(0xffffffffu, bt0.x, 0);
    const float inv1pb0 = 1.0f / (1.0f + beta0);
    float4 ba0 = bt0, ba1 = bt1;               // beta + origin
    if (lane == 0) ba0.x += 1.0f;

    #pragma unroll 2
    for (int i = 0; i < RPW; i += 2) {
        const int rA = base + i, rB = rA + 1;
        float4 aA = X[(size_t)rA * 64 + lane];
        float4 bA = X[(size_t)rA * 64 + 32 + lane];
        float4 aB = X[(size_t)rB * 64 + lane];
        float4 bB = X[(size_t)rB * 64 + 32 + lane];
        float4 scA = g_rowsc[rA];   // (fac, fac*alpha, coef)
        float4 scB = g_rowsc[rB];

        // t' = scale * (fac*x - fa*m - coef*ma)
        float4 tA0, tA1, tB0, tB1;
        tA0.x = sc0.x * (scA.x*aA.x - scA.y*m0.x - scA.z*ma0.x);
        tA0.y = sc0.y * (scA.x*aA.y - scA.y*m0.y - scA.z*ma0.y);
        tA0.z = sc0.z * (scA.x*aA.z - scA.y*m0.z - scA.z*ma0.z);
        tA0.w = sc0.w * (scA.x*aA.w - scA.y*m0.w - scA.z*ma0.w);
        tA1.x = sc1.x * (scA.x*bA.x - scA.y*m1.x - scA.z*ma1.x);
        tA1.y = sc1.y * (scA.x*bA.y - scA.y*m1.y - scA.z*ma1.y);
        tA1.z = sc1.z * (scA.x*bA.z - scA.y*m1.z - scA.z*ma1.z);
        tA1.w = sc1.w * (scA.x*bA.w - scA.y*m1.w - scA.z*ma1.w);
        tB0.x = sc0.x * (scB.x*aB.x - scB.y*m0.x - scB.z*ma0.x);
        tB0.y = sc0.y * (scB.x*aB.y - scB.y*m0.y - scB.z*ma0.y);
        tB0.z = sc0.z * (scB.x*aB.z - scB.y*m0.z - scB.z*ma0.z);
        tB0.w = sc0.w * (scB.x*aB.w - scB.y*m0.w - scB.z*ma0.w);
        tB1.x = sc1.x * (scB.x*bB.x - scB.y*m1.x - scB.z*ma1.x);
        tB1.y = sc1.y * (scB.x*bB.y - scB.y*m1.y - scB.z*ma1.y);
        tB1.z = sc1.z * (scB.x*bB.z - scB.y*m1.z - scB.z*ma1.z);
        tB1.w = sc1.w * (scB.x*bB.w - scB.y*m1.w - scB.z*ma1.w);

        // one interleaved reduction round: <beta,t'>_E and sum(t'^2) for both rows
        float dbA = tA0.x*bt0.x + tA0.y*bt0.y + tA0.z*bt0.z + tA0.w*bt0.w
                  + tA1.x*bt1.x + tA1.y*bt1.y + tA1.z*bt1.z + tA1.w*bt1.w;
        float ttA = tA0.x*tA0.x + tA0.y*tA0.y + tA0.z*tA0.z + tA0.w*tA0.w
                  + tA1.x*tA1.x + tA1.y*tA1.y + tA1.z*tA1.z + tA1.w*tA1.w;
        float dbB = tB0.x*bt0.x + tB0.y*bt0.y + tB0.z*bt0.z + tB0.w*bt0.w
                  + tB1.x*bt1.x + tB1.y*bt1.y + tB1.z*bt1.z + tB1.w*bt1.w;
        float ttB = tB0.x*tB0.x + tB0.y*tB0.y + tB0.z*tB0.z + tB0.w*tB0.w
                  + tB1.x*tB1.x + tB1.y*tB1.y + tB1.z*tB1.z + tB1.w*tB1.w;
        wsum4(dbA, ttA, dbB, ttB);

        float t0A = __shfl_sync(0xffffffffu, tA0.x, 0);   // time component of t'
        float t0B = __shfl_sync(0xffffffffu, tB0.x, 0);

        float lbA = dbA - 2.0f * beta0 * t0A;             // linner(beta, t')
        float lbB = dbB - 2.0f * beta0 * t0B;
        float c2A = lbA * inv1pb0;
        float c2B = lbB * inv1pb0;
        float uuA = ttA - 2.0f * t0A * t0A - 2.0f * c2A * t0A;   // linner(u,u)
        float uuB = ttB - 2.0f * t0B * t0B - 2.0f * c2B * t0B;

        float nA = sqrtf(fmaxf(uuA, 1e-7f));
        float nB = sqrtf(fmaxf(uuB, 1e-7f));
        float epA = expf(nA), emA = 1.0f / epA;
        float epB = expf(nB), emB = 1.0f / epB;
        float chA = 0.5f * (epA + emA), shA = 0.5f * (epA - emA) / nA;
        float chB = 0.5f * (epB + emB), shB = 0.5f * (epB - emB) / nB;

        float4 oA0, oA1, oB0, oB1;
        oA0.x = chA*bt0.x + shA*(tA0.x + c2A*ba0.x); oA0.y = chA*bt0.y + shA*(tA0.y + c2A*ba0.y);
        oA0.z = chA*bt0.z + shA*(tA0.z + c2A*ba0.z); oA0.w = chA*bt0.w + shA*(tA0.w + c2A*ba0.w);
        oA1.x = chA*bt1.x + shA*(tA1.x + c2A*ba1.x); oA1.y = chA*bt1.y + shA*(tA1.y + c2A*ba1.y);
        oA1.z = chA*bt1.z + shA*(tA1.z + c2A*ba1.z); oA1.w = chA*bt1.w + shA*(tA1.w + c2A*ba1.w);
        oB0.x = chB*bt0.x + shB*(tB0.x + c2B*ba0.x); oB0.y = chB*bt0.y + shB*(tB0.y + c2B*ba0.y);
        oB0.z = chB*bt0.z + shB*(tB0.z + c2B*ba0.z); oB0.w = chB*bt0.w + shB*(tB0.w + c2B*ba0.w);
        oB1.x = chB*bt1.x + shB*(tB1.x + c2B*ba1.x); oB1.y = chB*bt1.y + shB*(tB1.y + c2B*ba1.y);
        oB1.z = chB*bt1.z + shB*(tB1.z + c2B*ba1.z); oB1.w = chB*bt1.w + shB*(tB1.w + c2B*ba1.w);

        O[(size_t)rA * 64 + lane] = oA0;
        O[(size_t)rA * 64 + 32 + lane] = oA1;
        O[(size_t)rB * 64 + lane] = oB0;
        O[(size_t)rB * 64 + 32 + lane] = oB1;
    }
}

// ---------------- launch ----------------
extern "C" void kernel_launch(void* const* d_in, const int* in_sizes, int n_in,
                              void* d_out, int out_size) {
    const float* x     = (const float*)d_in[0];
    const float* beta  = (const float*)d_in[1];
    const float* gamma = (const float*)d_in[2];
    float* out = (float*)d_out;
    (void)in_sizes; (void)n_in; (void)out_size;

    k_sum_seq<<<BATCH * NCHUNK, THREADS>>>(x);
    k_centroid_b<<<BATCH, THREADS>>>();
    k_centroid_mean<<<1, THREADS>>>();
    k_stats<<<GBLOCKS, THREADS>>>(x);
    k_var<<<D, THREADS>>>(gamma);
    k_final<<<GBLOCKS, THREADS>>>(x, beta, out);
}